// round 1
// baseline (speedup 1.0000x reference)
#include <cuda_runtime.h>

#define NMAX 50000
#define EMAX 800000

// ---------------- scratch (static device arrays; no allocation) ----------------
__device__ float g_h1[NMAX * 64];
__device__ float g_h2[NMAX * 64];
__device__ float g_as1[NMAX * 2];
__device__ float g_ad1[NMAX * 2];
__device__ float g_den1[NMAX * 2];
__device__ float g_w1[EMAX * 2];
__device__ float g_hm[NMAX * 16];
__device__ float g_hl[NMAX * 16];
__device__ float g_ams[NMAX];
__device__ float g_amd[NMAX];
__device__ float g_als[NMAX];
__device__ float g_ald[NMAX];
__device__ float g_denm[NMAX];
__device__ float g_denl[NMAX];
__device__ float g_w2[EMAX * 2];
__device__ int   g_deg[NMAX];
__device__ int   g_rowptr[NMAX];
__device__ int   g_cursor[NMAX];
__device__ int   g_col[EMAX];
__device__ int   g_row[EMAX];
__device__ int   g_bsum[64];
__device__ int   g_bofs[64];
__device__ int   g_e64;   // 1 if edge_index is int64, 0 if int32

__device__ __forceinline__ float leakyf(float x) { return x > 0.f ? x : 0.2f * x; }

__device__ __forceinline__ int load_edge(const void* ei, long long idx) {
    if (g_e64) return (int)((const long long*)ei)[idx];
    return ((const int*)ei)[idx];
}

// ---------------- dtype detection ----------------
__global__ void k_detect(const void* ei, int E, int N) {
    if (threadIdx.x == 0 && blockIdx.x == 0) {
        const long long* p = (const long long*)ei;
        int ok = 1;
        int cnt = E < 256 ? E : 256;
        for (int i = 0; i < cnt; i++) {
            long long v = p[i];
            if (v < 0 || v >= (long long)N) { ok = 0; break; }
        }
        g_e64 = ok;
    }
}

// ---------------- CSR build ----------------
__global__ void k_zero(int N) {
    int i = blockIdx.x * blockDim.x + threadIdx.x;
    if (i < N) {
        g_deg[i] = 0;
        g_den1[2 * i] = 0.f; g_den1[2 * i + 1] = 0.f;
        g_denm[i] = 0.f; g_denl[i] = 0.f;
    }
}

__global__ void k_hist(const void* ei, int E) {
    int i = blockIdx.x * blockDim.x + threadIdx.x;
    if (i < E) {
        int d = load_edge(ei, (long long)E + i);
        atomicAdd(&g_deg[d], 1);
    }
}

__global__ void k_scan1(int N) {
    __shared__ int sd[1024];
    int i = blockIdx.x * 1024 + threadIdx.x;
    int v = (i < N) ? g_deg[i] : 0;
    sd[threadIdx.x] = v;
    __syncthreads();
    for (int o = 1; o < 1024; o <<= 1) {
        int t = (threadIdx.x >= o) ? sd[threadIdx.x - o] : 0;
        __syncthreads();
        sd[threadIdx.x] += t;
        __syncthreads();
    }
    if (i < N) g_rowptr[i] = sd[threadIdx.x] - v;   // exclusive within block
    if (threadIdx.x == 1023) g_bsum[blockIdx.x] = sd[1023];
}

__global__ void k_scan2(int nb) {
    if (threadIdx.x == 0 && blockIdx.x == 0) {
        int run = 0;
        for (int b = 0; b < nb; b++) { int t = g_bsum[b]; g_bofs[b] = run; run += t; }
    }
}

__global__ void k_scan3(int N) {
    int i = blockIdx.x * blockDim.x + threadIdx.x;
    if (i < N) {
        int r = g_rowptr[i] + g_bofs[i >> 10];
        g_rowptr[i] = r;
        g_cursor[i] = r;
    }
}

// ---------------- GEMM1: h1 = x @ W1 ; a_src1/a_dst1 per node ----------------
__global__ __launch_bounds__(256) void k_gemm1(
    const float* __restrict__ x, const float* __restrict__ W,
    const float* __restrict__ att_s, const float* __restrict__ att_d, int M)
{
    __shared__ float As[16][68];
    __shared__ float Bs[16][64];
    __shared__ float s_s[64][2];
    __shared__ float s_d[64][2];
    int tid = threadIdx.x;
    int tx = tid & 15, ty = tid >> 4;
    int m0 = blockIdx.x * 64;
    float acc[4][4];
#pragma unroll
    for (int i = 0; i < 4; i++)
#pragma unroll
        for (int j = 0; j < 4; j++) acc[i][j] = 0.f;

    int arow = tid >> 2;   // 0..63
    int ac4  = tid & 3;    // float4 slot within 16-wide k tile
    for (int k0 = 0; k0 < 128; k0 += 16) {
        float4 av = make_float4(0.f, 0.f, 0.f, 0.f);
        int gm = m0 + arow;
        if (gm < M) av = *reinterpret_cast<const float4*>(x + (size_t)gm * 128 + k0 + ac4 * 4);
        As[ac4 * 4 + 0][arow] = av.x;
        As[ac4 * 4 + 1][arow] = av.y;
        As[ac4 * 4 + 2][arow] = av.z;
        As[ac4 * 4 + 3][arow] = av.w;
        *reinterpret_cast<float4*>(&Bs[tid >> 4][(tid & 15) * 4]) =
            *reinterpret_cast<const float4*>(W + (size_t)(k0 + (tid >> 4)) * 64 + (tid & 15) * 4);
        __syncthreads();
#pragma unroll
        for (int k = 0; k < 16; k++) {
            float4 a = *reinterpret_cast<float4*>(&As[k][ty * 4]);
            float4 b = *reinterpret_cast<float4*>(&Bs[k][tx * 4]);
            float a4[4] = {a.x, a.y, a.z, a.w};
            float b4[4] = {b.x, b.y, b.z, b.w};
#pragma unroll
            for (int i = 0; i < 4; i++)
#pragma unroll
                for (int j = 0; j < 4; j++) acc[i][j] += a4[i] * b4[j];
        }
        __syncthreads();
    }

    if (tid < 128) { s_s[tid >> 1][tid & 1] = 0.f; s_d[tid >> 1][tid & 1] = 0.f; }
    __syncthreads();

    int head = tx >> 3;   // cols [0,32) head0, [32,64) head1; att arrays are contiguous 64
    float asv[4], adv[4];
#pragma unroll
    for (int j = 0; j < 4; j++) { asv[j] = att_s[tx * 4 + j]; adv[j] = att_d[tx * 4 + j]; }
#pragma unroll
    for (int i = 0; i < 4; i++) {
        int r = ty * 4 + i;
        int gm = m0 + r;
        float ps = 0.f, pd = 0.f;
#pragma unroll
        for (int j = 0; j < 4; j++) { ps += acc[i][j] * asv[j]; pd += acc[i][j] * adv[j]; }
        atomicAdd(&s_s[r][head], ps);
        atomicAdd(&s_d[r][head], pd);
        if (gm < M)
            *reinterpret_cast<float4*>(&g_h1[(size_t)gm * 64 + tx * 4]) =
                make_float4(acc[i][0], acc[i][1], acc[i][2], acc[i][3]);
    }
    __syncthreads();
    if (tid < 128) {
        int r = tid >> 1, h = tid & 1;
        int gm = m0 + r;
        if (gm < M) { g_as1[gm * 2 + h] = s_s[r][h]; g_ad1[gm * 2 + h] = s_d[r][h]; }
    }
}

// ---------------- scatter + layer-1 edge weights ----------------
__global__ void k_scatter(const void* ei, int E) {
    int i = blockIdx.x * blockDim.x + threadIdx.x;
    if (i >= E) return;
    int s = load_edge(ei, i);
    int d = load_edge(ei, (long long)E + i);
    int pos = atomicAdd(&g_cursor[d], 1);
    g_col[pos] = s;
    g_row[pos] = d;
    float w0 = __expf(leakyf(g_as1[2 * s]     + g_ad1[2 * d]));
    float w1 = __expf(leakyf(g_as1[2 * s + 1] + g_ad1[2 * d + 1]));
    g_w1[2 * pos] = w0; g_w1[2 * pos + 1] = w1;
    atomicAdd(&g_den1[2 * d], w0);
    atomicAdd(&g_den1[2 * d + 1], w1);
}

// ---------------- layer-1 aggregation: warp per node ----------------
__global__ __launch_bounds__(256) void k_agg1(const float* __restrict__ b1, int N) {
    int w = (blockIdx.x * blockDim.x + threadIdx.x) >> 5;
    int lane = threadIdx.x & 31;
    if (w >= N) return;
    int n = w;
    int start = g_rowptr[n];
    int degn = g_deg[n];
    float ws0 = __expf(leakyf(g_as1[2 * n]     + g_ad1[2 * n]));
    float ws1 = __expf(leakyf(g_as1[2 * n + 1] + g_ad1[2 * n + 1]));
    float inv0 = 1.f / (g_den1[2 * n]     + ws0 + 1e-16f);
    float inv1 = 1.f / (g_den1[2 * n + 1] + ws1 + 1e-16f);
    float acc0 = ws0 * g_h1[(size_t)n * 64 + lane];
    float acc1 = ws1 * g_h1[(size_t)n * 64 + 32 + lane];
#pragma unroll 4
    for (int i = 0; i < degn; i++) {
        int s = g_col[start + i];
        float2 wv = *reinterpret_cast<const float2*>(&g_w1[2 * (start + i)]);
        acc0 += wv.x * g_h1[(size_t)s * 64 + lane];
        acc1 += wv.y * g_h1[(size_t)s * 64 + 32 + lane];
    }
    float v0 = acc0 * inv0 + b1[lane];
    float v1 = acc1 * inv1 + b1[32 + lane];
    g_h2[(size_t)n * 64 + lane]      = v0 > 0.f ? v0 : 0.f;
    g_h2[(size_t)n * 64 + 32 + lane] = v1 > 0.f ? v1 : 0.f;
}

// ---------------- GEMM2: [hm | hl] = h2 @ [W_mu | W_ls] + att scalars ----------------
__global__ __launch_bounds__(256) void k_gemm2(
    const float* __restrict__ Wmu, const float* __restrict__ Wls,
    const float* __restrict__ asmu, const float* __restrict__ admu,
    const float* __restrict__ asls, const float* __restrict__ adls, int M)
{
    __shared__ float As[16][132];
    __shared__ float Bs[16][32];
    __shared__ float s_ms[128], s_md[128], s_lsm[128], s_ldm[128];
    int tid = threadIdx.x;
    int tx = tid & 7, ty = tid >> 3;  // tx 0..7 (x4 cols = 32), ty 0..31 (x4 rows = 128)
    int m0 = blockIdx.x * 128;
    float acc[4][4];
#pragma unroll
    for (int i = 0; i < 4; i++)
#pragma unroll
        for (int j = 0; j < 4; j++) acc[i][j] = 0.f;

    int arow = tid >> 2;   // 0..63
    int ac4  = tid & 3;
    for (int k0 = 0; k0 < 64; k0 += 16) {
#pragma unroll
        for (int h = 0; h < 2; h++) {
            int r = arow + h * 64;
            int gm = m0 + r;
            float4 av = make_float4(0.f, 0.f, 0.f, 0.f);
            if (gm < M) av = *reinterpret_cast<const float4*>(&g_h2[(size_t)gm * 64 + k0 + ac4 * 4]);
            As[ac4 * 4 + 0][r] = av.x;
            As[ac4 * 4 + 1][r] = av.y;
            As[ac4 * 4 + 2][r] = av.z;
            As[ac4 * 4 + 3][r] = av.w;
        }
#pragma unroll
        for (int h = 0; h < 2; h++) {
            int idx = tid + h * 256;
            int kk = idx >> 5, c = idx & 31;
            Bs[kk][c] = (c < 16) ? Wmu[(size_t)(k0 + kk) * 16 + c]
                                 : Wls[(size_t)(k0 + kk) * 16 + (c - 16)];
        }
        __syncthreads();
#pragma unroll
        for (int k = 0; k < 16; k++) {
            float4 a = *reinterpret_cast<float4*>(&As[k][ty * 4]);
            float4 b = *reinterpret_cast<float4*>(&Bs[k][tx * 4]);
            float a4[4] = {a.x, a.y, a.z, a.w};
            float b4[4] = {b.x, b.y, b.z, b.w};
#pragma unroll
            for (int i = 0; i < 4; i++)
#pragma unroll
                for (int j = 0; j < 4; j++) acc[i][j] += a4[i] * b4[j];
        }
        __syncthreads();
    }

    if (tid < 128) { s_ms[tid] = 0.f; s_md[tid] = 0.f; s_lsm[tid] = 0.f; s_ldm[tid] = 0.f; }
    __syncthreads();

    bool is_mu = (tx < 4);
    int cb = (tx & 3) * 4;
    const float* ap_s = is_mu ? asmu : asls;
    const float* ap_d = is_mu ? admu : adls;
    float vs[4], vd[4];
#pragma unroll
    for (int j = 0; j < 4; j++) { vs[j] = ap_s[cb + j]; vd[j] = ap_d[cb + j]; }
    float* s_ps = is_mu ? s_ms : s_lsm;
    float* s_pd = is_mu ? s_md : s_ldm;
    float* H = is_mu ? g_hm : g_hl;
#pragma unroll
    for (int i = 0; i < 4; i++) {
        int r = ty * 4 + i;
        int gm = m0 + r;
        float ps = 0.f, pd = 0.f;
#pragma unroll
        for (int j = 0; j < 4; j++) { ps += acc[i][j] * vs[j]; pd += acc[i][j] * vd[j]; }
        atomicAdd(&s_ps[r], ps);
        atomicAdd(&s_pd[r], pd);
        if (gm < M)
            *reinterpret_cast<float4*>(&H[(size_t)gm * 16 + cb]) =
                make_float4(acc[i][0], acc[i][1], acc[i][2], acc[i][3]);
    }
    __syncthreads();
    if (tid < 128) {
        int gm = m0 + tid;
        if (gm < M) {
            g_ams[gm] = s_ms[tid];  g_amd[gm] = s_md[tid];
            g_als[gm] = s_lsm[tid]; g_ald[gm] = s_ldm[tid];
        }
    }
}

// ---------------- layer-2 edge weights ----------------
__global__ void k_edgew2(int E) {
    int i = blockIdx.x * blockDim.x + threadIdx.x;
    if (i >= E) return;
    int s = g_col[i], d = g_row[i];
    float wm = __expf(leakyf(g_ams[s] + g_amd[d]));
    float wl = __expf(leakyf(g_als[s] + g_ald[d]));
    g_w2[2 * i] = wm; g_w2[2 * i + 1] = wl;
    atomicAdd(&g_denm[d], wm);
    atomicAdd(&g_denl[d], wl);
}

// ---------------- layer-2 aggregation: warp per node, lanes 0-15 mu / 16-31 ls ----------------
__global__ __launch_bounds__(256) void k_agg2(
    const float* __restrict__ bmu, const float* __restrict__ bls,
    float* __restrict__ out, int N)
{
    int w = (blockIdx.x * blockDim.x + threadIdx.x) >> 5;
    int lane = threadIdx.x & 31;
    if (w >= N) return;
    int n = w;
    int start = g_rowptr[n];
    int degn = g_deg[n];
    float wsm = __expf(leakyf(g_ams[n] + g_amd[n]));
    float wsl = __expf(leakyf(g_als[n] + g_ald[n]));
    float invm = 1.f / (g_denm[n] + wsm + 1e-16f);
    float invl = 1.f / (g_denl[n] + wsl + 1e-16f);
    bool is_mu = lane < 16;
    int c = lane & 15;
    const float* H = is_mu ? g_hm : g_hl;
    float wself = is_mu ? wsm : wsl;
    float inv   = is_mu ? invm : invl;
    float acc = wself * H[(size_t)n * 16 + c];
#pragma unroll 4
    for (int i = 0; i < degn; i++) {
        int s = g_col[start + i];
        float2 wv = *reinterpret_cast<const float2*>(&g_w2[2 * (start + i)]);
        float ww = is_mu ? wv.x : wv.y;
        acc += ww * H[(size_t)s * 16 + c];
    }
    float res = acc * inv + (is_mu ? bmu[c] : bls[c]);
    if (is_mu) out[(size_t)n * 16 + c] = res;
    else       out[(size_t)N * 16 + (size_t)n * 16 + c] = res;
}

// ---------------- launch ----------------
extern "C" void kernel_launch(void* const* d_in, const int* in_sizes, int n_in,
                              void* d_out, int out_size) {
    const float* x    = (const float*)d_in[0];
    const void*  ei   = d_in[1];
    const float* W1   = (const float*)d_in[2];
    const float* as1  = (const float*)d_in[3];
    const float* ad1  = (const float*)d_in[4];
    const float* b1   = (const float*)d_in[5];
    const float* Wmu  = (const float*)d_in[6];
    const float* asmu = (const float*)d_in[7];
    const float* admu = (const float*)d_in[8];
    const float* bmu  = (const float*)d_in[9];
    const float* Wls  = (const float*)d_in[10];
    const float* asls = (const float*)d_in[11];
    const float* adls = (const float*)d_in[12];
    const float* bls  = (const float*)d_in[13];
    int N = in_sizes[0] / 128;
    int E = in_sizes[1] / 2;
    float* out = (float*)d_out;

    const int TB = 256;
    k_detect<<<1, 32>>>(ei, E, N);
    k_zero<<<(N + TB - 1) / TB, TB>>>(N);
    k_hist<<<(E + TB - 1) / TB, TB>>>(ei, E);
    int nb = (N + 1023) / 1024;
    k_scan1<<<nb, 1024>>>(N);
    k_scan2<<<1, 32>>>(nb);
    k_scan3<<<(N + TB - 1) / TB, TB>>>(N);
    k_gemm1<<<(N + 63) / 64, 256>>>(x, W1, as1, ad1, N);
    k_scatter<<<(E + TB - 1) / TB, TB>>>(ei, E);
    k_agg1<<<(N * 32 + TB - 1) / TB, TB>>>(b1, N);
    k_gemm2<<<(N + 127) / 128, 256>>>(Wmu, Wls, asmu, admu, asls, adls, N);
    k_edgew2<<<(E + TB - 1) / TB, TB>>>(E);
    k_agg2<<<(N * 32 + TB - 1) / TB, TB>>>(bmu, bls, out, N);
}

// round 2
// speedup vs baseline: 1.1444x; 1.1444x over previous
#include <cuda_runtime.h>

#define NMAX 50000
#define EMAX 800000

// ---------------- scratch ----------------
__device__ float  g_h1[NMAX * 64];
__device__ float  g_h2[NMAX * 64];
__device__ float2 g_as1[NMAX];     // layer-1 src attention scalars (2 heads)
__device__ float2 g_ad1[NMAX];     // layer-1 dst attention scalars
__device__ float  g_hm[NMAX * 16];
__device__ float  g_hl[NMAX * 16];
__device__ float2 g_a2s[NMAX];     // {mu_src, ls_src}
__device__ float2 g_a2d[NMAX];     // {mu_dst, ls_dst}
__device__ int    g_deg[NMAX];
__device__ int    g_rowptr[NMAX];
__device__ int    g_cursor[NMAX];
__device__ int    g_col[EMAX];
__device__ int    g_bsum[64];
__device__ int    g_bofs[64];
__device__ int    g_e64;

__device__ __forceinline__ float leakyf(float x) { return x > 0.f ? x : 0.2f * x; }

__device__ __forceinline__ int load_edge(const void* ei, long long idx) {
    if (g_e64) return (int)((const long long*)ei)[idx];
    return ((const int*)ei)[idx];
}

// ---------------- init: zero deg + dtype detection ----------------
__global__ void k_init(const void* ei, int E, int N) {
    int i = blockIdx.x * blockDim.x + threadIdx.x;
    if (i < N) g_deg[i] = 0;
    if (i == 0) {
        const long long* p = (const long long*)ei;
        int ok = 1;
        int cnt = E < 256 ? E : 256;
        for (int k = 0; k < cnt; k++) {
            long long v = p[k];
            if (v < 0 || v >= (long long)N) { ok = 0; break; }
        }
        g_e64 = ok;
    }
}

__global__ void k_hist(const void* ei, int E) {
    int i = blockIdx.x * blockDim.x + threadIdx.x;
    if (i < E) {
        int d = load_edge(ei, (long long)E + i);
        atomicAdd(&g_deg[d], 1);
    }
}

// ---------------- scan (shfl-based, 1024/block) ----------------
__global__ void k_scan1(int N) {
    __shared__ int warp_sums[32];
    int i = blockIdx.x * 1024 + threadIdx.x;
    int lane = threadIdx.x & 31, wid = threadIdx.x >> 5;
    int v = (i < N) ? g_deg[i] : 0;
    int incl = v;
#pragma unroll
    for (int o = 1; o < 32; o <<= 1) {
        int t = __shfl_up_sync(0xffffffffu, incl, o);
        if (lane >= o) incl += t;
    }
    if (lane == 31) warp_sums[wid] = incl;
    __syncthreads();
    if (wid == 0) {
        int s = warp_sums[lane];
        int si = s;
#pragma unroll
        for (int o = 1; o < 32; o <<= 1) {
            int t = __shfl_up_sync(0xffffffffu, si, o);
            if (lane >= o) si += t;
        }
        warp_sums[lane] = si - s;   // exclusive
        if (lane == 31) g_bsum[blockIdx.x] = si;
    }
    __syncthreads();
    if (i < N) g_rowptr[i] = incl - v + warp_sums[wid];
}

__global__ void k_scan2(int nb) {
    if (threadIdx.x == 0) {
        int run = 0;
        for (int b = 0; b < nb; b++) { int t = g_bsum[b]; g_bofs[b] = run; run += t; }
    }
}

__global__ void k_scan3(int N) {
    int i = blockIdx.x * blockDim.x + threadIdx.x;
    if (i < N) {
        int r = g_rowptr[i] + g_bofs[i >> 10];
        g_rowptr[i] = r;
        g_cursor[i] = r;
    }
}

// ---------------- GEMM1: h1 = x @ W1 ; per-node attention scalars ----------------
__global__ __launch_bounds__(256) void k_gemm1(
    const float* __restrict__ x, const float* __restrict__ W,
    const float* __restrict__ att_s, const float* __restrict__ att_d, int M)
{
    __shared__ float As[16][68];
    __shared__ float Bs[16][64];
    __shared__ float s_s[64][2];
    __shared__ float s_d[64][2];
    int tid = threadIdx.x;
    int tx = tid & 15, ty = tid >> 4;
    int m0 = blockIdx.x * 64;
    float acc[4][4];
#pragma unroll
    for (int i = 0; i < 4; i++)
#pragma unroll
        for (int j = 0; j < 4; j++) acc[i][j] = 0.f;

    int arow = tid >> 2;
    int ac4  = tid & 3;
    for (int k0 = 0; k0 < 128; k0 += 16) {
        float4 av = make_float4(0.f, 0.f, 0.f, 0.f);
        int gm = m0 + arow;
        if (gm < M) av = *reinterpret_cast<const float4*>(x + (size_t)gm * 128 + k0 + ac4 * 4);
        As[ac4 * 4 + 0][arow] = av.x;
        As[ac4 * 4 + 1][arow] = av.y;
        As[ac4 * 4 + 2][arow] = av.z;
        As[ac4 * 4 + 3][arow] = av.w;
        *reinterpret_cast<float4*>(&Bs[tid >> 4][(tid & 15) * 4]) =
            *reinterpret_cast<const float4*>(W + (size_t)(k0 + (tid >> 4)) * 64 + (tid & 15) * 4);
        __syncthreads();
#pragma unroll
        for (int k = 0; k < 16; k++) {
            float4 a = *reinterpret_cast<float4*>(&As[k][ty * 4]);
            float4 b = *reinterpret_cast<float4*>(&Bs[k][tx * 4]);
            float a4[4] = {a.x, a.y, a.z, a.w};
            float b4[4] = {b.x, b.y, b.z, b.w};
#pragma unroll
            for (int i = 0; i < 4; i++)
#pragma unroll
                for (int j = 0; j < 4; j++) acc[i][j] += a4[i] * b4[j];
        }
        __syncthreads();
    }

    if (tid < 128) { s_s[tid >> 1][tid & 1] = 0.f; s_d[tid >> 1][tid & 1] = 0.f; }
    __syncthreads();

    int head = tx >> 3;
    float asv[4], adv[4];
#pragma unroll
    for (int j = 0; j < 4; j++) { asv[j] = att_s[tx * 4 + j]; adv[j] = att_d[tx * 4 + j]; }
#pragma unroll
    for (int i = 0; i < 4; i++) {
        int r = ty * 4 + i;
        int gm = m0 + r;
        float ps = 0.f, pd = 0.f;
#pragma unroll
        for (int j = 0; j < 4; j++) { ps += acc[i][j] * asv[j]; pd += acc[i][j] * adv[j]; }
        atomicAdd(&s_s[r][head], ps);
        atomicAdd(&s_d[r][head], pd);
        if (gm < M)
            *reinterpret_cast<float4*>(&g_h1[(size_t)gm * 64 + tx * 4]) =
                make_float4(acc[i][0], acc[i][1], acc[i][2], acc[i][3]);
    }
    __syncthreads();
    if (tid < 64) {
        int gm = m0 + tid;
        if (gm < M) {
            g_as1[gm] = make_float2(s_s[tid][0], s_s[tid][1]);
            g_ad1[gm] = make_float2(s_d[tid][0], s_d[tid][1]);
        }
    }
}

// ---------------- scatter: CSR column fill only ----------------
__global__ void k_scatter(const void* ei, int E) {
    int i = blockIdx.x * blockDim.x + threadIdx.x;
    if (i >= E) return;
    int s = load_edge(ei, i);
    int d = load_edge(ei, (long long)E + i);
    int pos = atomicAdd(&g_cursor[d], 1);
    g_col[pos] = s;
}

// ---------------- layer-1 agg: warp/node, fused softmax, no atomics ----------------
__global__ __launch_bounds__(256) void k_agg1(const float* __restrict__ b1, int N) {
    int n = (blockIdx.x * blockDim.x + threadIdx.x) >> 5;
    int lane = threadIdx.x & 31;
    if (n >= N) return;
    int start = g_rowptr[n];
    int deg = g_deg[n];
    float2 ad = g_ad1[n];
    float2 as = g_as1[n];
    float ws0 = __expf(leakyf(as.x + ad.x));
    float ws1 = __expf(leakyf(as.y + ad.y));
    float den0 = ws0, den1 = ws1;
    float acc0 = ws0 * g_h1[(size_t)n * 64 + lane];
    float acc1 = ws1 * g_h1[(size_t)n * 64 + 32 + lane];
    for (int base = 0; base < deg; base += 32) {
        int i = base + lane;
        int s = 0; float w0 = 0.f, w1 = 0.f;
        if (i < deg) {
            s = g_col[start + i];
            float2 a = g_as1[s];
            w0 = __expf(leakyf(a.x + ad.x));
            w1 = __expf(leakyf(a.y + ad.y));
        }
        int cnt = min(32, deg - base);
#pragma unroll 4
        for (int j = 0; j < cnt; j++) {
            int sj    = __shfl_sync(0xffffffffu, s, j);
            float w0j = __shfl_sync(0xffffffffu, w0, j);
            float w1j = __shfl_sync(0xffffffffu, w1, j);
            den0 += w0j; den1 += w1j;
            acc0 += w0j * g_h1[(size_t)sj * 64 + lane];
            acc1 += w1j * g_h1[(size_t)sj * 64 + 32 + lane];
        }
    }
    float v0 = acc0 * (1.f / (den0 + 1e-16f)) + b1[lane];
    float v1 = acc1 * (1.f / (den1 + 1e-16f)) + b1[32 + lane];
    g_h2[(size_t)n * 64 + lane]      = v0 > 0.f ? v0 : 0.f;
    g_h2[(size_t)n * 64 + 32 + lane] = v1 > 0.f ? v1 : 0.f;
}

// ---------------- GEMM2: [hm | hl] = h2 @ [W_mu | W_ls] + att scalars ----------------
__global__ __launch_bounds__(256) void k_gemm2(
    const float* __restrict__ Wmu, const float* __restrict__ Wls,
    const float* __restrict__ asmu, const float* __restrict__ admu,
    const float* __restrict__ asls, const float* __restrict__ adls, int M)
{
    __shared__ float As[16][132];
    __shared__ float Bs[16][32];
    __shared__ float s_ms[128], s_md[128], s_lsm[128], s_ldm[128];
    int tid = threadIdx.x;
    int tx = tid & 7, ty = tid >> 3;
    int m0 = blockIdx.x * 128;
    float acc[4][4];
#pragma unroll
    for (int i = 0; i < 4; i++)
#pragma unroll
        for (int j = 0; j < 4; j++) acc[i][j] = 0.f;

    int arow = tid >> 2;
    int ac4  = tid & 3;
    for (int k0 = 0; k0 < 64; k0 += 16) {
#pragma unroll
        for (int h = 0; h < 2; h++) {
            int r = arow + h * 64;
            int gm = m0 + r;
            float4 av = make_float4(0.f, 0.f, 0.f, 0.f);
            if (gm < M) av = *reinterpret_cast<const float4*>(&g_h2[(size_t)gm * 64 + k0 + ac4 * 4]);
            As[ac4 * 4 + 0][r] = av.x;
            As[ac4 * 4 + 1][r] = av.y;
            As[ac4 * 4 + 2][r] = av.z;
            As[ac4 * 4 + 3][r] = av.w;
        }
#pragma unroll
        for (int h = 0; h < 2; h++) {
            int idx = tid + h * 256;
            int kk = idx >> 5, c = idx & 31;
            Bs[kk][c] = (c < 16) ? Wmu[(size_t)(k0 + kk) * 16 + c]
                                 : Wls[(size_t)(k0 + kk) * 16 + (c - 16)];
        }
        __syncthreads();
#pragma unroll
        for (int k = 0; k < 16; k++) {
            float4 a = *reinterpret_cast<float4*>(&As[k][ty * 4]);
            float4 b = *reinterpret_cast<float4*>(&Bs[k][tx * 4]);
            float a4[4] = {a.x, a.y, a.z, a.w};
            float b4[4] = {b.x, b.y, b.z, b.w};
#pragma unroll
            for (int i = 0; i < 4; i++)
#pragma unroll
                for (int j = 0; j < 4; j++) acc[i][j] += a4[i] * b4[j];
        }
        __syncthreads();
    }

    if (tid < 128) { s_ms[tid] = 0.f; s_md[tid] = 0.f; s_lsm[tid] = 0.f; s_ldm[tid] = 0.f; }
    __syncthreads();

    bool is_mu = (tx < 4);
    int cb = (tx & 3) * 4;
    const float* ap_s = is_mu ? asmu : asls;
    const float* ap_d = is_mu ? admu : adls;
    float vs[4], vd[4];
#pragma unroll
    for (int j = 0; j < 4; j++) { vs[j] = ap_s[cb + j]; vd[j] = ap_d[cb + j]; }
    float* s_ps = is_mu ? s_ms : s_lsm;
    float* s_pd = is_mu ? s_md : s_ldm;
    float* H = is_mu ? g_hm : g_hl;
#pragma unroll
    for (int i = 0; i < 4; i++) {
        int r = ty * 4 + i;
        int gm = m0 + r;
        float ps = 0.f, pd = 0.f;
#pragma unroll
        for (int j = 0; j < 4; j++) { ps += acc[i][j] * vs[j]; pd += acc[i][j] * vd[j]; }
        atomicAdd(&s_ps[r], ps);
        atomicAdd(&s_pd[r], pd);
        if (gm < M)
            *reinterpret_cast<float4*>(&H[(size_t)gm * 16 + cb]) =
                make_float4(acc[i][0], acc[i][1], acc[i][2], acc[i][3]);
    }
    __syncthreads();
    if (tid < 128) {
        int gm = m0 + tid;
        if (gm < M) {
            g_a2s[gm] = make_float2(s_ms[tid], s_lsm[tid]);
            g_a2d[gm] = make_float2(s_md[tid], s_ldm[tid]);
        }
    }
}

// ---------------- layer-2 agg: warp/node, fused softmax for mu+ls ----------------
__global__ __launch_bounds__(256) void k_agg2(
    const float* __restrict__ bmu, const float* __restrict__ bls,
    float* __restrict__ out, int N)
{
    int n = (blockIdx.x * blockDim.x + threadIdx.x) >> 5;
    int lane = threadIdx.x & 31;
    if (n >= N) return;
    int start = g_rowptr[n];
    int deg = g_deg[n];
    float2 ad = g_a2d[n];
    float2 as = g_a2s[n];
    float wsm = __expf(leakyf(as.x + ad.x));
    float wsl = __expf(leakyf(as.y + ad.y));
    bool is_mu = lane < 16;
    int c = lane & 15;
    const float* H = is_mu ? g_hm : g_hl;
    float wself = is_mu ? wsm : wsl;
    float den = wself;
    float acc = wself * H[(size_t)n * 16 + c];
    for (int base = 0; base < deg; base += 32) {
        int i = base + lane;
        int s = 0; float wm = 0.f, wl = 0.f;
        if (i < deg) {
            s = g_col[start + i];
            float2 a = g_a2s[s];
            wm = __expf(leakyf(a.x + ad.x));
            wl = __expf(leakyf(a.y + ad.y));
        }
        int cnt = min(32, deg - base);
#pragma unroll 4
        for (int j = 0; j < cnt; j++) {
            int sj    = __shfl_sync(0xffffffffu, s, j);
            float wmj = __shfl_sync(0xffffffffu, wm, j);
            float wlj = __shfl_sync(0xffffffffu, wl, j);
            float ww = is_mu ? wmj : wlj;
            den += ww;
            acc += ww * H[(size_t)sj * 16 + c];
        }
    }
    float res = acc * (1.f / (den + 1e-16f)) + (is_mu ? bmu[c] : bls[c]);
    if (is_mu) out[(size_t)n * 16 + c] = res;
    else       out[(size_t)N * 16 + (size_t)n * 16 + c] = res;
}

// ---------------- launch ----------------
extern "C" void kernel_launch(void* const* d_in, const int* in_sizes, int n_in,
                              void* d_out, int out_size) {
    const float* x    = (const float*)d_in[0];
    const void*  ei   = d_in[1];
    const float* W1   = (const float*)d_in[2];
    const float* as1  = (const float*)d_in[3];
    const float* ad1  = (const float*)d_in[4];
    const float* b1   = (const float*)d_in[5];
    const float* Wmu  = (const float*)d_in[6];
    const float* asmu = (const float*)d_in[7];
    const float* admu = (const float*)d_in[8];
    const float* bmu  = (const float*)d_in[9];
    const float* Wls  = (const float*)d_in[10];
    const float* asls = (const float*)d_in[11];
    const float* adls = (const float*)d_in[12];
    const float* bls  = (const float*)d_in[13];
    int N = in_sizes[0] / 128;
    int E = in_sizes[1] / 2;
    float* out = (float*)d_out;

    const int TB = 256;
    k_init<<<(N + TB - 1) / TB, TB>>>(ei, E, N);
    k_hist<<<(E + TB - 1) / TB, TB>>>(ei, E);
    int nb = (N + 1023) / 1024;
    k_scan1<<<nb, 1024>>>(N);
    k_scan2<<<1, 32>>>(nb);
    k_scan3<<<(N + TB - 1) / TB, TB>>>(N);
    k_gemm1<<<(N + 63) / 64, 256>>>(x, W1, as1, ad1, N);
    k_scatter<<<(E + TB - 1) / TB, TB>>>(ei, E);
    k_agg1<<<(N * 32 + TB - 1) / TB, TB>>>(b1, N);
    k_gemm2<<<(N + 127) / 128, 256>>>(Wmu, Wls, asmu, admu, asls, adls, N);
    k_agg2<<<(N * 32 + TB - 1) / TB, TB>>>(bmu, bls, out, N);
}

// round 3
// speedup vs baseline: 1.3344x; 1.1660x over previous
#include <cuda_runtime.h>

#define NMAX 50000
#define EMAX 800000

// ---------------- scratch ----------------
__device__ float  g_h1[NMAX * 64];
__device__ float  g_h2[NMAX * 64];
__device__ float2 g_as1[NMAX];
__device__ float2 g_ad1[NMAX];
__device__ float  g_h3[NMAX * 32];   // interleaved [mu(16) | ls(16)] per node
__device__ float2 g_a2s[NMAX];
__device__ float2 g_a2d[NMAX];
__device__ int    g_deg[NMAX];
__device__ int    g_rowptr[NMAX];
__device__ int    g_cursor[NMAX];
__device__ int    g_col[EMAX];
__device__ int    g_bsum[64];
__device__ int    g_e64;

__device__ __forceinline__ float leakyf(float x) { return x > 0.f ? x : 0.2f * x; }

__device__ __forceinline__ int load_edge(const void* ei, long long idx) {
    if (g_e64) return (int)((const long long*)ei)[idx];
    return ((const int*)ei)[idx];
}

// ---------------- init: zero deg + dtype detection ----------------
__global__ void k_init(const void* ei, int E, int N) {
    int i = blockIdx.x * blockDim.x + threadIdx.x;
    if (i < N) g_deg[i] = 0;
    if (i == 0) {
        const long long* p = (const long long*)ei;
        int ok = 1;
        int cnt = E < 256 ? E : 256;
        for (int k = 0; k < cnt; k++) {
            long long v = p[k];
            if (v < 0 || v >= (long long)N) { ok = 0; break; }
        }
        g_e64 = ok;
    }
}

__global__ void k_hist(const void* ei, int E) {
    int i = blockIdx.x * blockDim.x + threadIdx.x;
    if (i < E) {
        int d = load_edge(ei, (long long)E + i);
        atomicAdd(&g_deg[d], 1);
    }
}

// ---------------- scan phase 1: per-block exclusive + block sums ----------------
__global__ void k_scan1(int N) {
    __shared__ int warp_sums[32];
    int i = blockIdx.x * 1024 + threadIdx.x;
    int lane = threadIdx.x & 31, wid = threadIdx.x >> 5;
    int v = (i < N) ? g_deg[i] : 0;
    int incl = v;
#pragma unroll
    for (int o = 1; o < 32; o <<= 1) {
        int t = __shfl_up_sync(0xffffffffu, incl, o);
        if (lane >= o) incl += t;
    }
    if (lane == 31) warp_sums[wid] = incl;
    __syncthreads();
    if (wid == 0) {
        int s = warp_sums[lane];
        int si = s;
#pragma unroll
        for (int o = 1; o < 32; o <<= 1) {
            int t = __shfl_up_sync(0xffffffffu, si, o);
            if (lane >= o) si += t;
        }
        warp_sums[lane] = si - s;   // exclusive
        if (lane == 31) g_bsum[blockIdx.x] = si;
    }
    __syncthreads();
    if (i < N) g_rowptr[i] = incl - v + warp_sums[wid];
}

// ---------------- scan phase 2+3 fused: each block computes its own offset ----------------
__global__ void k_scan23(int N, int nb) {
    __shared__ int s_ofs;
    int b = blockIdx.x;
    if (threadIdx.x < 32) {
        int lane = threadIdx.x;
        int p = 0;
        if (lane < b && lane < nb)           p += g_bsum[lane];
        if (lane + 32 < b && lane + 32 < nb) p += g_bsum[lane + 32];
#pragma unroll
        for (int o = 16; o > 0; o >>= 1) p += __shfl_down_sync(0xffffffffu, p, o);
        if (lane == 0) s_ofs = p;
    }
    __syncthreads();
    int i = b * 1024 + threadIdx.x;
    if (i < N) {
        int r = g_rowptr[i] + s_ofs;
        g_rowptr[i] = r;
        g_cursor[i] = r;
    }
}

// ---------------- GEMM1: h1 = x @ W1 ; per-node attention scalars ----------------
__global__ __launch_bounds__(256) void k_gemm1(
    const float* __restrict__ x, const float* __restrict__ W,
    const float* __restrict__ att_s, const float* __restrict__ att_d, int M)
{
    __shared__ float As[16][68];
    __shared__ float Bs[16][64];
    __shared__ float s_s[64][2];
    __shared__ float s_d[64][2];
    int tid = threadIdx.x;
    int tx = tid & 15, ty = tid >> 4;
    int m0 = blockIdx.x * 64;
    float acc[4][4];
#pragma unroll
    for (int i = 0; i < 4; i++)
#pragma unroll
        for (int j = 0; j < 4; j++) acc[i][j] = 0.f;

    int arow = tid >> 2;
    int ac4  = tid & 3;
    for (int k0 = 0; k0 < 128; k0 += 16) {
        float4 av = make_float4(0.f, 0.f, 0.f, 0.f);
        int gm = m0 + arow;
        if (gm < M) av = *reinterpret_cast<const float4*>(x + (size_t)gm * 128 + k0 + ac4 * 4);
        As[ac4 * 4 + 0][arow] = av.x;
        As[ac4 * 4 + 1][arow] = av.y;
        As[ac4 * 4 + 2][arow] = av.z;
        As[ac4 * 4 + 3][arow] = av.w;
        *reinterpret_cast<float4*>(&Bs[tid >> 4][(tid & 15) * 4]) =
            *reinterpret_cast<const float4*>(W + (size_t)(k0 + (tid >> 4)) * 64 + (tid & 15) * 4);
        __syncthreads();
#pragma unroll
        for (int k = 0; k < 16; k++) {
            float4 a = *reinterpret_cast<float4*>(&As[k][ty * 4]);
            float4 b = *reinterpret_cast<float4*>(&Bs[k][tx * 4]);
            float a4[4] = {a.x, a.y, a.z, a.w};
            float b4[4] = {b.x, b.y, b.z, b.w};
#pragma unroll
            for (int i = 0; i < 4; i++)
#pragma unroll
                for (int j = 0; j < 4; j++) acc[i][j] += a4[i] * b4[j];
        }
        __syncthreads();
    }

    if (tid < 128) { s_s[tid >> 1][tid & 1] = 0.f; s_d[tid >> 1][tid & 1] = 0.f; }
    __syncthreads();

    int head = tx >> 3;
    float asv[4], adv[4];
#pragma unroll
    for (int j = 0; j < 4; j++) { asv[j] = att_s[tx * 4 + j]; adv[j] = att_d[tx * 4 + j]; }
#pragma unroll
    for (int i = 0; i < 4; i++) {
        int r = ty * 4 + i;
        int gm = m0 + r;
        float ps = 0.f, pd = 0.f;
#pragma unroll
        for (int j = 0; j < 4; j++) { ps += acc[i][j] * asv[j]; pd += acc[i][j] * adv[j]; }
        atomicAdd(&s_s[r][head], ps);
        atomicAdd(&s_d[r][head], pd);
        if (gm < M)
            *reinterpret_cast<float4*>(&g_h1[(size_t)gm * 64 + tx * 4]) =
                make_float4(acc[i][0], acc[i][1], acc[i][2], acc[i][3]);
    }
    __syncthreads();
    if (tid < 64) {
        int gm = m0 + tid;
        if (gm < M) {
            g_as1[gm] = make_float2(s_s[tid][0], s_s[tid][1]);
            g_ad1[gm] = make_float2(s_d[tid][0], s_d[tid][1]);
        }
    }
}

// ---------------- scatter: CSR column fill ----------------
__global__ void k_scatter(const void* ei, int E) {
    int i = blockIdx.x * blockDim.x + threadIdx.x;
    if (i >= E) return;
    int s = load_edge(ei, i);
    int d = load_edge(ei, (long long)E + i);
    int pos = atomicAdd(&g_cursor[d], 1);
    g_col[pos] = s;
}

// ---------------- layer-1 agg: warp/node, fused softmax, smem-staged weights ----------------
__global__ __launch_bounds__(256) void k_agg1(const float* __restrict__ b1, int N) {
    __shared__ float4 stage[8][32];
    int n = (blockIdx.x * blockDim.x + threadIdx.x) >> 5;
    int lane = threadIdx.x & 31;
    int w = threadIdx.x >> 5;
    if (n >= N) return;
    int start = g_rowptr[n];
    int deg = g_deg[n];
    float2 ad = g_ad1[n];
    float2 as = g_as1[n];
    float ws0 = __expf(leakyf(as.x + ad.x));
    float ws1 = __expf(leakyf(as.y + ad.y));
    float den0 = ws0, den1 = ws1;
    float acc0 = ws0 * g_h1[(size_t)n * 64 + lane];
    float acc1 = ws1 * g_h1[(size_t)n * 64 + 32 + lane];
    for (int base = 0; base < deg; base += 32) {
        int i = base + lane;
        float4 st = make_float4(0.f, 0.f, 0.f, 0.f);
        if (i < deg) {
            int s = g_col[start + i];
            float2 a = g_as1[s];
            st.x = __int_as_float(s);
            st.y = __expf(leakyf(a.x + ad.x));
            st.z = __expf(leakyf(a.y + ad.y));
        }
        stage[w][lane] = st;
        __syncwarp();
        int cnt = min(32, deg - base);
#pragma unroll 4
        for (int j = 0; j < cnt; j++) {
            float4 v = stage[w][j];
            int sj = __float_as_int(v.x);
            den0 += v.y; den1 += v.z;
            acc0 += v.y * g_h1[(size_t)sj * 64 + lane];
            acc1 += v.z * g_h1[(size_t)sj * 64 + 32 + lane];
        }
        __syncwarp();
    }
    float v0 = acc0 * (1.f / (den0 + 1e-16f)) + b1[lane];
    float v1 = acc1 * (1.f / (den1 + 1e-16f)) + b1[32 + lane];
    g_h2[(size_t)n * 64 + lane]      = v0 > 0.f ? v0 : 0.f;
    g_h2[(size_t)n * 64 + 32 + lane] = v1 > 0.f ? v1 : 0.f;
}

// ---------------- GEMM2: h3 = h2 @ [W_mu | W_ls] interleaved; att scalars ----------------
__global__ __launch_bounds__(256) void k_gemm2(
    const float* __restrict__ Wmu, const float* __restrict__ Wls,
    const float* __restrict__ asmu, const float* __restrict__ admu,
    const float* __restrict__ asls, const float* __restrict__ adls, int M)
{
    __shared__ float As[16][132];
    __shared__ float Bs[16][32];
    __shared__ float s_ms[128], s_md[128], s_lsm[128], s_ldm[128];
    int tid = threadIdx.x;
    int tx = tid & 7, ty = tid >> 3;
    int m0 = blockIdx.x * 128;
    float acc[4][4];
#pragma unroll
    for (int i = 0; i < 4; i++)
#pragma unroll
        for (int j = 0; j < 4; j++) acc[i][j] = 0.f;

    int arow = tid >> 2;
    int ac4  = tid & 3;
    for (int k0 = 0; k0 < 64; k0 += 16) {
#pragma unroll
        for (int h = 0; h < 2; h++) {
            int r = arow + h * 64;
            int gm = m0 + r;
            float4 av = make_float4(0.f, 0.f, 0.f, 0.f);
            if (gm < M) av = *reinterpret_cast<const float4*>(&g_h2[(size_t)gm * 64 + k0 + ac4 * 4]);
            As[ac4 * 4 + 0][r] = av.x;
            As[ac4 * 4 + 1][r] = av.y;
            As[ac4 * 4 + 2][r] = av.z;
            As[ac4 * 4 + 3][r] = av.w;
        }
#pragma unroll
        for (int h = 0; h < 2; h++) {
            int idx = tid + h * 256;
            int kk = idx >> 5, c = idx & 31;
            Bs[kk][c] = (c < 16) ? Wmu[(size_t)(k0 + kk) * 16 + c]
                                 : Wls[(size_t)(k0 + kk) * 16 + (c - 16)];
        }
        __syncthreads();
#pragma unroll
        for (int k = 0; k < 16; k++) {
            float4 a = *reinterpret_cast<float4*>(&As[k][ty * 4]);
            float4 b = *reinterpret_cast<float4*>(&Bs[k][tx * 4]);
            float a4[4] = {a.x, a.y, a.z, a.w};
            float b4[4] = {b.x, b.y, b.z, b.w};
#pragma unroll
            for (int i = 0; i < 4; i++)
#pragma unroll
                for (int j = 0; j < 4; j++) acc[i][j] += a4[i] * b4[j];
        }
        __syncthreads();
    }

    if (tid < 128) { s_ms[tid] = 0.f; s_md[tid] = 0.f; s_lsm[tid] = 0.f; s_ldm[tid] = 0.f; }
    __syncthreads();

    bool is_mu = (tx < 4);
    int cb = (tx & 3) * 4;
    const float* ap_s = is_mu ? asmu : asls;
    const float* ap_d = is_mu ? admu : adls;
    float vs[4], vd[4];
#pragma unroll
    for (int j = 0; j < 4; j++) { vs[j] = ap_s[cb + j]; vd[j] = ap_d[cb + j]; }
    float* s_ps = is_mu ? s_ms : s_lsm;
    float* s_pd = is_mu ? s_md : s_ldm;
    int col0 = (is_mu ? 0 : 16) + cb;
#pragma unroll
    for (int i = 0; i < 4; i++) {
        int r = ty * 4 + i;
        int gm = m0 + r;
        float ps = 0.f, pd = 0.f;
#pragma unroll
        for (int j = 0; j < 4; j++) { ps += acc[i][j] * vs[j]; pd += acc[i][j] * vd[j]; }
        atomicAdd(&s_ps[r], ps);
        atomicAdd(&s_pd[r], pd);
        if (gm < M)
            *reinterpret_cast<float4*>(&g_h3[(size_t)gm * 32 + col0]) =
                make_float4(acc[i][0], acc[i][1], acc[i][2], acc[i][3]);
    }
    __syncthreads();
    if (tid < 128) {
        int gm = m0 + tid;
        if (gm < M) {
            g_a2s[gm] = make_float2(s_ms[tid], s_lsm[tid]);
            g_a2d[gm] = make_float2(s_md[tid], s_ldm[tid]);
        }
    }
}

// ---------------- layer-2 agg: warp/node, interleaved h3 gather ----------------
__global__ __launch_bounds__(256) void k_agg2(
    const float* __restrict__ bmu, const float* __restrict__ bls,
    float* __restrict__ out, int N)
{
    __shared__ float4 stage[8][32];
    int n = (blockIdx.x * blockDim.x + threadIdx.x) >> 5;
    int lane = threadIdx.x & 31;
    int w = threadIdx.x >> 5;
    if (n >= N) return;
    int start = g_rowptr[n];
    int deg = g_deg[n];
    float2 ad = g_a2d[n];
    float2 as = g_a2s[n];
    float wsm = __expf(leakyf(as.x + ad.x));
    float wsl = __expf(leakyf(as.y + ad.y));
    bool is_mu = lane < 16;
    int c = lane & 15;
    float wself = is_mu ? wsm : wsl;
    float den = wself;
    float acc = wself * g_h3[(size_t)n * 32 + lane];
    for (int base = 0; base < deg; base += 32) {
        int i = base + lane;
        float4 st = make_float4(0.f, 0.f, 0.f, 0.f);
        if (i < deg) {
            int s = g_col[start + i];
            float2 a = g_a2s[s];
            st.x = __int_as_float(s);
            st.y = __expf(leakyf(a.x + ad.x));
            st.z = __expf(leakyf(a.y + ad.y));
        }
        stage[w][lane] = st;
        __syncwarp();
        int cnt = min(32, deg - base);
#pragma unroll 4
        for (int j = 0; j < cnt; j++) {
            float4 v = stage[w][j];
            int sj = __float_as_int(v.x);
            float ww = is_mu ? v.y : v.z;
            den += ww;
            acc += ww * g_h3[(size_t)sj * 32 + lane];
        }
        __syncwarp();
    }
    float res = acc * (1.f / (den + 1e-16f)) + (is_mu ? bmu[c] : bls[c]);
    if (is_mu) out[(size_t)n * 16 + c] = res;
    else       out[(size_t)N * 16 + (size_t)n * 16 + c] = res;
}

// ---------------- launch ----------------
extern "C" void kernel_launch(void* const* d_in, const int* in_sizes, int n_in,
                              void* d_out, int out_size) {
    const float* x    = (const float*)d_in[0];
    const void*  ei   = d_in[1];
    const float* W1   = (const float*)d_in[2];
    const float* as1  = (const float*)d_in[3];
    const float* ad1  = (const float*)d_in[4];
    const float* b1   = (const float*)d_in[5];
    const float* Wmu  = (const float*)d_in[6];
    const float* asmu = (const float*)d_in[7];
    const float* admu = (const float*)d_in[8];
    const float* bmu  = (const float*)d_in[9];
    const float* Wls  = (const float*)d_in[10];
    const float* asls = (const float*)d_in[11];
    const float* adls = (const float*)d_in[12];
    const float* bls  = (const float*)d_in[13];
    int N = in_sizes[0] / 128;
    int E = in_sizes[1] / 2;
    float* out = (float*)d_out;

    static cudaStream_t s2 = nullptr;
    static cudaEvent_t evF = nullptr, evJ = nullptr;
    if (s2 == nullptr) {
        cudaStreamCreateWithFlags(&s2, cudaStreamNonBlocking);
        cudaEventCreateWithFlags(&evF, cudaEventDisableTiming);
        cudaEventCreateWithFlags(&evJ, cudaEventDisableTiming);
    }

    const int TB = 256;
    int nb = (N + 1023) / 1024;

    // fork: gemm1 (depends only on inputs) runs concurrently with CSR build
    cudaEventRecord(evF, 0);
    cudaStreamWaitEvent(s2, evF, 0);

    k_init<<<(N + TB - 1) / TB, TB>>>(ei, E, N);               // idx0
    k_hist<<<(E + TB - 1) / TB, TB>>>(ei, E);                  // idx1
    k_scan1<<<nb, 1024>>>(N);                                  // idx2
    k_gemm1<<<(N + 63) / 64, 256, 0, s2>>>(x, W1, as1, ad1, N);// idx3 (profiled)
    k_scan23<<<nb, 1024>>>(N, nb);                             // idx4
    k_scatter<<<(E + TB - 1) / TB, TB>>>(ei, E);               // idx5

    // join
    cudaEventRecord(evJ, s2);
    cudaStreamWaitEvent(0, evJ, 0);

    k_agg1<<<(N * 32 + TB - 1) / TB, TB>>>(b1, N);             // idx6
    k_gemm2<<<(N + 127) / 128, 256>>>(Wmu, Wls, asmu, admu, asls, adls, N); // idx7
    k_agg2<<<(N * 32 + TB - 1) / TB, TB>>>(bmu, bls, out, N);  // idx8
}